// round 11
// baseline (speedup 1.0000x reference)
#include <cuda_runtime.h>

// LogLinearAttention — algebraic collapse (exact; rel_err=0 every round):
//   softmax over axis=1 then sum over axis=1 => attention columns sum to 1:
//     out[b] = sigmoid( xsum[b,:]·c + S*(br·Wl) + bl )
//   xsum[b,e] = sum_s x[b,s,e],  c[e] = sum_d Wl[d]*Wr[d,e].  q/v dead.
//
// R10: totals were pinned at ~12.8us across every 3-kernel variant ->
// fixed per-launch costs dominate. Collapse to ONE kernel: 128 c-blocks +
// 296 streaming blocks (validated loop, xsum-then-dot), producer counter
// for c, last-block-done final. Counters reset each launch for graph replay.

#define BB 8
#define SS 2048
#define DD 512
#define DD4 (DD / 4)              // 128 float4 columns
#define JPB 37                    // row-range blocks per batch
#define NBLK (BB * JPB)           // 296 streaming blocks
#define CBLK_D 16                 // d-chunks for c partials
#define DCH (DD / CBLK_D)         // 32 d rows per chunk
#define ECH4 16                   // 16 float4 cols per c-chunk (8 e-chunks)
#define NCB 128                   // c blocks (16 d-chunks x 8 e-chunks)
#define GRID (NCB + NBLK)         // 424 blocks, all co-resident

__device__ float g_cpart[CBLK_D * DD];  // c partials over d-chunks (32 KB)
__device__ float g_dots[NBLK];          // per-block partial dots
__device__ int   g_cdone;               // c-chunk completion counter
__device__ int   g_done;                // streaming-block completion counter

__global__ void __launch_bounds__(256) k_all(
    const float* __restrict__ x,
    const float* __restrict__ Wr,
    const float* __restrict__ Wl,
    const float* __restrict__ br,
    const float* __restrict__ bl,
    float* __restrict__ out)
{
    const int blk = blockIdx.x;
    const int tid = threadIdx.x;

    if (blk < NCB) {
        // ── c-partial block (jd, je): d rows [jd*32,+32), f4 cols [je*16,+16) ──
        const int jd = blk >> 3;                  // 0..15
        const int je = blk & 7;                   // 0..7
        const int td = tid >> 4;                  // d-subgroup 0..15 (2 rows each)
        const int tf = tid & 15;                  // float4 col in chunk

        const int e4 = je * ECH4 + tf;
        float4 acc = make_float4(0.f, 0.f, 0.f, 0.f);
#pragma unroll
        for (int k = 0; k < 2; ++k) {
            const int d = jd * DCH + td * 2 + k;
            const float wl = __ldg(&Wl[d]);
            const float4 w = reinterpret_cast<const float4*>(Wr)[(size_t)d * DD4 + e4];
            acc.x += wl * w.x; acc.y += wl * w.y; acc.z += wl * w.z; acc.w += wl * w.w;
        }

        __shared__ float4 s[16][ECH4];            // 4 KB
        s[td][tf] = acc;
        __syncthreads();
#pragma unroll
        for (int off = 8; off > 0; off >>= 1) {
            if (td < off) {
                float4 a = s[td][tf], b2 = s[td + off][tf];
                s[td][tf] = make_float4(a.x + b2.x, a.y + b2.y, a.z + b2.z, a.w + b2.w);
            }
            __syncthreads();
        }
        if (td == 0) {
            reinterpret_cast<float4*>(g_cpart)[(size_t)jd * DD4 + e4] = s[0][tf];
            __threadfence();                      // publish this writer's data
        }
        __syncthreads();
        if (tid == 0) atomicAdd(&g_cdone, 1);
        return;
    }

    // ── streaming block: validated loop, xsum accumulation ──
    const int sb  = blk - NCB;
    const int b   = sb / JPB;
    const int j   = sb % JPB;
    const int col = tid & (DD4 - 1);          // float4 column 0..127
    const int r0  = tid >> 7;                 // 0 or 1

    const int r_begin = (j * SS) / JPB;
    const int r_end   = ((j + 1) * SS) / JPB;
    const float4* xb  = reinterpret_cast<const float4*>(x + (size_t)b * SS * DD);

    float4 acc = make_float4(0.f, 0.f, 0.f, 0.f);
    int r = r_begin + r0;
#pragma unroll 4
    for (; r < r_end; r += 2) {               // continuous stream, MLP_p1 ~ 4
        float4 v = xb[(size_t)r * DD4 + col];
        acc.x += v.x; acc.y += v.y; acc.z += v.z; acc.w += v.w;
    }

    // wait for c (c finishes ~1-2us into the ~6us stream -> no real wait)
    if (tid == 0) {
        while (*(volatile int*)&g_cdone < NCB) { }
    }
    __syncthreads();
    __threadfence();

    // fold c for this column, dot with the xsum partial
    float4 c4 = make_float4(0.f, 0.f, 0.f, 0.f);
#pragma unroll
    for (int jd = 0; jd < CBLK_D; ++jd) {
        float4 v = reinterpret_cast<const float4*>(g_cpart)[(size_t)jd * DD4 + col];
        c4.x += v.x; c4.y += v.y; c4.z += v.z; c4.w += v.w;
    }
    float val = acc.x * c4.x + acc.y * c4.y + acc.z * c4.z + acc.w * c4.w;

    // block-reduce 256 scalars
#pragma unroll
    for (int off = 16; off > 0; off >>= 1)
        val += __shfl_down_sync(0xffffffffu, val, off);
    __shared__ float warp_s[8];
    if ((tid & 31) == 0) warp_s[tid >> 5] = val;
    __syncthreads();

    __shared__ int s_last;
    if (tid == 0) {
        float t = warp_s[0];
#pragma unroll
        for (int i = 1; i < 8; ++i) t += warp_s[i];
        g_dots[sb] = t;
        __threadfence();
        s_last = (atomicAdd(&g_done, 1) == NBLK - 1);
    }
    __syncthreads();
    if (!s_last) return;

    // ── last block: finisher (bias dot + per-batch fold + sigmoid) ──
    __threadfence();

    __shared__ float bias_w[4];
    __shared__ float s_bias;
    if (tid < 128) {
        const float4 br4 = reinterpret_cast<const float4*>(br)[tid];
        const float4 wl4 = reinterpret_cast<const float4*>(Wl)[tid];
        float bv = br4.x * wl4.x + br4.y * wl4.y + br4.z * wl4.z + br4.w * wl4.w;
#pragma unroll
        for (int off = 16; off > 0; off >>= 1)
            bv += __shfl_down_sync(0xffffffffu, bv, off);
        if ((tid & 31) == 0) bias_w[tid >> 5] = bv;
    }
    __syncthreads();
    if (tid == 0) s_bias = bias_w[0] + bias_w[1] + bias_w[2] + bias_w[3];
    __syncthreads();

    // warp w = batch w (8 warps, 8 batches); lanes fold 37 dots
    const int w    = tid >> 5;
    const int lane = tid & 31;
    float d = (lane < JPB) ? g_dots[w * JPB + lane] : 0.f;
    if (lane + 32 < JPB) d += g_dots[w * JPB + lane + 32];   // lanes 0..4
#pragma unroll
    for (int off = 16; off > 0; off >>= 1)
        d += __shfl_down_sync(0xffffffffu, d, off);
    if (lane == 0) {
        float z = d + (float)SS * s_bias + bl[0];
        out[w] = 1.0f / (1.0f + expf(-z));
    }

    // reset counters for the next graph replay
    __syncthreads();
    if (tid == 0) { g_done = 0; g_cdone = 0; }
}

extern "C" void kernel_launch(void* const* d_in, const int* in_sizes, int n_in,
                              void* d_out, int out_size)
{
    // metadata order: x, Wq, bq, Wv, bv, Wr, br, Wl, bl
    const float* x  = (const float*)d_in[0];
    const float* Wr = (const float*)d_in[5];
    const float* br = (const float*)d_in[6];
    const float* Wl = (const float*)d_in[7];
    const float* bl = (const float*)d_in[8];
    float* out = (float*)d_out;

    k_all<<<GRID, 256>>>(x, Wr, Wl, br, bl, out);
}

// round 12
// speedup vs baseline: 1.0663x; 1.0663x over previous
#include <cuda_runtime.h>

// LogLinearAttention — algebraic collapse (exact; rel_err=0 every round):
//   softmax over axis=1 then sum over axis=1 => attention columns sum to 1:
//     out[b] = sigmoid( xsum[b,:]·c + S*(br·Wl) + bl )
//   xsum[b,e] = sum_s x[b,s,e],  c[e] = sum_d Wl[d]*Wr[d,e].  q/v dead.
//
// R11: single kernel, EXACTLY 296 blocks (2/SM, perfectly balanced wave —
// every fused regression so far had 384/424-block imbalanced grids).
// c-duty rides as a prologue on 16 blocks per batch, compensated with
// shorter streaming row ranges (52 vs ~58 rows). Tail: guarded c-wait
// (no actual spin), fold c, dot, last-block finisher. One launch total.

#define BB 8
#define SS 2048
#define DD 512
#define DD4 (DD / 4)              // 128 float4 columns
#define JPB 37                    // blocks per batch
#define NBLK (BB * JPB)           // 296 = 2 * 148
#define NCD 16                    // c-duty blocks per batch (8*16 = 128 chunks)
#define CROWS 52                  // stream rows for c-duty blocks (16*52 = 832)
#define RREST 1216                // remaining rows per batch (2048 - 832)
#define CBLK_D 16                 // d-chunks
#define DCH 32                    // d rows per chunk
#define ECH4 16                   // float4 cols per chunk (8 e-chunks)
#define NCB 128                   // total c chunks

__device__ float g_cpart[CBLK_D * DD];  // c partials over d-chunks (32 KB)
__device__ float g_dots[NBLK];          // per-block partial dots
__device__ int   g_cdone;               // c-chunk completion counter
__device__ int   g_done;                // block completion counter

__global__ void __launch_bounds__(256) k_all(
    const float* __restrict__ x,
    const float* __restrict__ Wr,
    const float* __restrict__ Wl,
    const float* __restrict__ br,
    const float* __restrict__ bl,
    float* __restrict__ out)
{
    const int blk = blockIdx.x;
    const int tid = threadIdx.x;
    const int b   = blk / JPB;
    const int j   = blk % JPB;

    // ── c-duty prologue: blocks with j < 16 compute one c-chunk ──
    if (j < NCD) {
        const int cb = b * NCD + j;               // 0..127
        const int jd = cb >> 3;                   // d-chunk 0..15
        const int je = cb & 7;                    // e-chunk 0..7
        const int td = tid >> 4;                  // d-subgroup 0..15 (2 rows each)
        const int tf = tid & 15;                  // float4 col in chunk

        const int e4 = je * ECH4 + tf;
        float4 acc = make_float4(0.f, 0.f, 0.f, 0.f);
#pragma unroll
        for (int k = 0; k < 2; ++k) {
            const int d = jd * DCH + td * 2 + k;
            const float wl = __ldg(&Wl[d]);
            const float4 w = reinterpret_cast<const float4*>(Wr)[(size_t)d * DD4 + e4];
            acc.x += wl * w.x; acc.y += wl * w.y; acc.z += wl * w.z; acc.w += wl * w.w;
        }

        __shared__ float4 s[16][ECH4];            // 4 KB
        s[td][tf] = acc;
        __syncthreads();
#pragma unroll
        for (int off = 8; off > 0; off >>= 1) {
            if (td < off) {
                float4 a = s[td][tf], b2 = s[td + off][tf];
                s[td][tf] = make_float4(a.x + b2.x, a.y + b2.y, a.z + b2.z, a.w + b2.w);
            }
            __syncthreads();
        }
        if (td == 0) {
            reinterpret_cast<float4*>(g_cpart)[(size_t)jd * DD4 + e4] = s[0][tf];
            __threadfence();
        }
        __syncthreads();
        if (tid == 0) atomicAdd(&g_cdone, 1);
        __syncthreads();
    }

    // ── streaming: validated loop shape, xsum accumulation in registers ──
    const int col = tid & (DD4 - 1);          // float4 column 0..127
    const int r0  = tid >> 7;                 // 0 or 1

    // compensated row partition: c-duty blocks get 52 rows, others ~58
    const int r_begin = (j < NCD) ? j * CROWS
                                  : NCD * CROWS + ((j - NCD) * RREST) / (JPB - NCD);
    const int r_end   = (j < NCD) ? (j + 1) * CROWS
                                  : NCD * CROWS + ((j - NCD + 1) * RREST) / (JPB - NCD);
    const float4* xb  = reinterpret_cast<const float4*>(x + (size_t)b * SS * DD);

    float4 acc = make_float4(0.f, 0.f, 0.f, 0.f);
    int r = r_begin + r0;
#pragma unroll 4
    for (; r < r_end; r += 2) {               // continuous stream, MLP_p1 ~ 4
        float4 v = xb[(size_t)r * DD4 + col];
        acc.x += v.x; acc.y += v.y; acc.z += v.z; acc.w += v.w;
    }

    // ── tail: guaranteed c availability (no actual spin in practice) ──
    if (tid == 0) {
        while (*(volatile int*)&g_cdone < NCB) { }
    }
    __syncthreads();
    __threadfence();

    float4 c4 = make_float4(0.f, 0.f, 0.f, 0.f);
#pragma unroll
    for (int jd = 0; jd < CBLK_D; ++jd) {
        float4 v = reinterpret_cast<const float4*>(g_cpart)[(size_t)jd * DD4 + col];
        c4.x += v.x; c4.y += v.y; c4.z += v.z; c4.w += v.w;
    }
    float val = acc.x * c4.x + acc.y * c4.y + acc.z * c4.z + acc.w * c4.w;

#pragma unroll
    for (int off = 16; off > 0; off >>= 1)
        val += __shfl_down_sync(0xffffffffu, val, off);
    __shared__ float warp_s[8];
    if ((tid & 31) == 0) warp_s[tid >> 5] = val;
    __syncthreads();

    __shared__ int s_last;
    if (tid == 0) {
        float t = warp_s[0];
#pragma unroll
        for (int i = 1; i < 8; ++i) t += warp_s[i];
        g_dots[blk] = t;
        __threadfence();
        s_last = (atomicAdd(&g_done, 1) == NBLK - 1);
    }
    __syncthreads();
    if (!s_last) return;

    // ── last block: bias dot + per-batch fold + sigmoid + counter reset ──
    __threadfence();

    __shared__ float bias_w[4];
    __shared__ float s_bias;
    if (tid < 128) {
        const float4 br4 = reinterpret_cast<const float4*>(br)[tid];
        const float4 wl4 = reinterpret_cast<const float4*>(Wl)[tid];
        float bv = br4.x * wl4.x + br4.y * wl4.y + br4.z * wl4.z + br4.w * wl4.w;
#pragma unroll
        for (int off = 16; off > 0; off >>= 1)
            bv += __shfl_down_sync(0xffffffffu, bv, off);
        if ((tid & 31) == 0) bias_w[tid >> 5] = bv;
    }
    __syncthreads();
    if (tid == 0) s_bias = bias_w[0] + bias_w[1] + bias_w[2] + bias_w[3];
    __syncthreads();

    // warp w = batch w (8 warps); lanes fold the 37 dots of that batch
    {
        const int w    = tid >> 5;
        const int lane = tid & 31;
        float d = (lane < JPB) ? g_dots[w * JPB + lane] : 0.f;
        if (lane + 32 < JPB) d += g_dots[w * JPB + lane + 32];   // lanes 0..4
#pragma unroll
        for (int off = 16; off > 0; off >>= 1)
            d += __shfl_down_sync(0xffffffffu, d, off);
        if (lane == 0) {
            float z = d + (float)SS * s_bias + bl[0];
            out[w] = 1.0f / (1.0f + expf(-z));
        }
    }

    __syncthreads();
    if (tid == 0) { g_done = 0; g_cdone = 0; }
}

extern "C" void kernel_launch(void* const* d_in, const int* in_sizes, int n_in,
                              void* d_out, int out_size)
{
    // metadata order: x, Wq, bq, Wv, bv, Wr, br, Wl, bl
    const float* x  = (const float*)d_in[0];
    const float* Wr = (const float*)d_in[5];
    const float* br = (const float*)d_in[6];
    const float* Wl = (const float*)d_in[7];
    const float* bl = (const float*)d_in[8];
    float* out = (float*)d_out;

    k_all<<<NBLK, 256>>>(x, Wr, Wl, br, bl, out);
}